// round 1
// baseline (speedup 1.0000x reference)
#include <cuda_runtime.h>
#include <cuda_bf16.h>

// ---------------- Problem constants ----------------
#define CB   4      // batch
#define CL   512    // seq len
#define CD   1024   // d_model
#define CED  2048   // expanded dim
#define CNS  16     // state dim N
#define CRK  64     // dt rank
#define CKC  4      // conv kernel
#define CML  (CB*CL)        // 2048 rows
#define BLED (CB*CL*CED)    // 4194304

// ---------------- Scratch (device globals; no allocation allowed) ----------
__device__ float g_xz[CB*CL*2*CED];     // 33.5 MB  (xf | zf)
__device__ float g_xc[2*BLED];          // 33.5 MB  conv+silu output, per dir
__device__ float g_dbc[2*CML*96];       // 1.6 MB   [delta_r | B | C]
__device__ float g_delta[2*BLED];       // 33.5 MB  softplus(delta)
__device__ float g_y[2*BLED];           // 33.5 MB  gated scan output per dir
__device__ float g_yc[BLED];            // 16.8 MB  combined

// ---------------- helpers ----------------
__device__ __forceinline__ float softplusf(float x) {
    return fmaxf(x, 0.f) + log1pf(__expf(-fabsf(x)));
}
__device__ __forceinline__ float siluf(float x) {
    return x / (1.f + __expf(-x));
}

// ---------------- Generic fp32 NT GEMM: C[M,N] = A[M,K] * B[N,K]^T --------
// EPI: 0 = none, 1 = softplus(acc + bias[n])
template<int BM, int BN, int BK, int TM, int TN, int EPI>
__global__ void __launch_bounds__((BM/TM)*(BN/TN))
sgemm_nt(const float* __restrict__ A, int lda,
         const float* __restrict__ B, int ldb,
         float* __restrict__ C, int ldc,
         int M, int N, int K,
         const float* __restrict__ bias)
{
    constexpr int THREADS = (BM/TM)*(BN/TN);
    __shared__ float As[BK][BM];
    __shared__ float Bs[BK][BN];

    const int tid = threadIdx.x;
    const int row0 = blockIdx.y * BM;
    const int col0 = blockIdx.x * BN;
    const int tx = tid % (BN/TN);
    const int ty = tid / (BN/TN);

    float acc[TM][TN];
#pragma unroll
    for (int i = 0; i < TM; i++)
#pragma unroll
        for (int j = 0; j < TN; j++) acc[i][j] = 0.f;

    for (int k0 = 0; k0 < K; k0 += BK) {
        // load A tile (float4 along K), store k-major
#pragma unroll
        for (int i = tid; i < BM*BK/4; i += THREADS) {
            int m  = i / (BK/4);
            int kq = (i % (BK/4)) * 4;
            float4 v = *(const float4*)&A[(size_t)(row0+m)*lda + k0 + kq];
            As[kq+0][m] = v.x; As[kq+1][m] = v.y;
            As[kq+2][m] = v.z; As[kq+3][m] = v.w;
        }
#pragma unroll
        for (int i = tid; i < BN*BK/4; i += THREADS) {
            int n  = i / (BK/4);
            int kq = (i % (BK/4)) * 4;
            float4 v = *(const float4*)&B[(size_t)(col0+n)*ldb + k0 + kq];
            Bs[kq+0][n] = v.x; Bs[kq+1][n] = v.y;
            Bs[kq+2][n] = v.z; Bs[kq+3][n] = v.w;
        }
        __syncthreads();

#pragma unroll
        for (int k = 0; k < BK; k++) {
            float ra[TM], rb[TN];
#pragma unroll
            for (int i = 0; i < TM; i++) ra[i] = As[k][ty*TM + i];
#pragma unroll
            for (int j = 0; j < TN; j++) rb[j] = Bs[k][tx*TN + j];
#pragma unroll
            for (int i = 0; i < TM; i++)
#pragma unroll
                for (int j = 0; j < TN; j++)
                    acc[i][j] = fmaf(ra[i], rb[j], acc[i][j]);
        }
        __syncthreads();
    }

#pragma unroll
    for (int i = 0; i < TM; i++) {
        int m = row0 + ty*TM + i;
#pragma unroll
        for (int j = 0; j < TN; j++) {
            int n = col0 + tx*TN + j;
            float v = acc[i][j];
            if (EPI == 1) v = softplusf(v + bias[n]);
            C[(size_t)m*ldc + n] = v;
        }
    }
}

// ---------------- causal depthwise conv + SiLU (both directions) ----------
// dir 0: input = xz[b, t, 0:ED] ; dir 1: input = xz[b, L-1-t, 0:ED]
__global__ void conv_silu_kernel(const float* __restrict__ xz,
                                 const float* __restrict__ cw0, const float* __restrict__ cb0,
                                 const float* __restrict__ cw1, const float* __restrict__ cb1,
                                 float* __restrict__ xc)
{
    int idx = blockIdx.x * blockDim.x + threadIdx.x;   // over 2*B*L*ED = 2^23
    int e   = idx & (CED-1);
    int t   = (idx >> 11) & (CL-1);
    int b   = (idx >> 20) & (CB-1);
    int dir = idx >> 22;

    const float* w = dir ? cw1 : cw0;
    float acc = (dir ? cb1 : cb0)[e];
#pragma unroll
    for (int j = 0; j < CKC; j++) {
        int ts = t - (CKC-1) + j;
        if (ts >= 0) {
            int tg = dir ? (CL-1-ts) : ts;
            acc = fmaf(w[e*CKC + j], xz[((size_t)(b*CL + tg) << 12) + e], acc);
        }
    }
    xc[idx] = siluf(acc);
}

// ---------------- selective scan (one thread = one channel e) -------------
#define SCAN_TC 16
__global__ void __launch_bounds__(128)
scan_kernel(const float* __restrict__ delta,   // [B*L, ED]
            const float* __restrict__ xc,      // [B*L, ED]
            const float* __restrict__ dbc,     // [B*L, 96]
            const float* __restrict__ xz,      // z at col ED..2ED
            const float* __restrict__ A_log,   // [ED, N]
            const float* __restrict__ Dp,      // [ED]
            float* __restrict__ y,             // [B*L, ED]
            int rev)
{
    __shared__ float sD[SCAN_TC][128];
    __shared__ float sX[SCAN_TC][128];
    __shared__ float sZ[SCAN_TC][128];
    __shared__ float sB[SCAN_TC][CNS];
    __shared__ float sC[SCAN_TC][CNS];

    const int e  = blockIdx.x * 128 + threadIdx.x;
    const int b  = blockIdx.y;
    const int tx = threadIdx.x;

    float Areg[CNS];
#pragma unroll
    for (int n = 0; n < CNS; n++) Areg[n] = -__expf(A_log[e*CNS + n]);
    const float Dpe = Dp[e];

    float h[CNS];
#pragma unroll
    for (int n = 0; n < CNS; n++) h[n] = 0.f;

    for (int t0 = 0; t0 < CL; t0 += SCAN_TC) {
        __syncthreads();
#pragma unroll
        for (int it = 0; it < SCAN_TC; it++) {
            int t = t0 + it;
            size_t r = (size_t)(b*CL + t) * CED + e;
            sD[it][tx] = delta[r];
            sX[it][tx] = xc[r];
            int tz = rev ? (CL-1-t) : t;
            sZ[it][tx] = xz[((size_t)(b*CL + tz) << 12) + CED + e];
        }
        for (int j = tx; j < SCAN_TC*CNS; j += 128) {
            int it = j >> 4, n = j & (CNS-1);
            size_t r = (size_t)(b*CL + t0 + it) * 96;
            sB[it][n] = dbc[r + CRK + n];
            sC[it][n] = dbc[r + CRK + CNS + n];
        }
        __syncthreads();

#pragma unroll
        for (int it = 0; it < SCAN_TC; it++) {
            float d  = sD[it][tx];
            float xv = sX[it][tx];
            float dx = d * xv;
            float y0 = 0.f, y1 = 0.f, y2 = 0.f, y3 = 0.f;
#pragma unroll
            for (int n = 0; n < CNS; n += 4) {
                float dA0 = __expf(d * Areg[n+0]);
                float dA1 = __expf(d * Areg[n+1]);
                float dA2 = __expf(d * Areg[n+2]);
                float dA3 = __expf(d * Areg[n+3]);
                h[n+0] = fmaf(dA0, h[n+0], dx * sB[it][n+0]);
                h[n+1] = fmaf(dA1, h[n+1], dx * sB[it][n+1]);
                h[n+2] = fmaf(dA2, h[n+2], dx * sB[it][n+2]);
                h[n+3] = fmaf(dA3, h[n+3], dx * sB[it][n+3]);
                y0 = fmaf(h[n+0], sC[it][n+0], y0);
                y1 = fmaf(h[n+1], sC[it][n+1], y1);
                y2 = fmaf(h[n+2], sC[it][n+2], y2);
                y3 = fmaf(h[n+3], sC[it][n+3], y3);
            }
            float zv = sZ[it][tx];
            float yo = ((y0+y1) + (y2+y3)) + Dpe * xv;
            y[(size_t)(b*CL + t0 + it)*CED + e] = yo * siluf(zv);
        }
    }
}

// ---------------- combine: yc = 0.5*(y_f + reverse(y_b)) ------------------
__global__ void combine_kernel(const float* __restrict__ y0,
                               const float* __restrict__ y1,
                               float* __restrict__ yc)
{
    int idx = blockIdx.x * blockDim.x + threadIdx.x;  // over B*L*ED
    int e = idx & (CED-1);
    int t = (idx >> 11) & (CL-1);
    int b = idx >> 20;
    float a = y0[idx];
    float bb = y1[(size_t)(b*CL + (CL-1-t))*CED + e];
    yc[idx] = 0.5f * (a + bb);
}

// ---------------- launch ----------------
extern "C" void kernel_launch(void* const* d_in, const int* in_sizes, int n_in,
                              void* d_out, int out_size)
{
    const float* x      = (const float*)d_in[0];
    const float* W_in   = (const float*)d_in[1];
    const float* conv_w = (const float*)d_in[2];
    const float* conv_b = (const float*)d_in[3];
    const float* Wx     = (const float*)d_in[4];
    const float* Wdt    = (const float*)d_in[5];
    const float* b_dt   = (const float*)d_in[6];
    const float* A_log  = (const float*)d_in[7];
    const float* Dp     = (const float*)d_in[8];
    const float* conv_w_b = (const float*)d_in[9];
    const float* conv_b_b = (const float*)d_in[10];
    const float* Wx_b   = (const float*)d_in[11];
    const float* Wdt_b  = (const float*)d_in[12];
    const float* b_dt_b = (const float*)d_in[13];
    const float* A_log_b= (const float*)d_in[14];
    const float* Dp_b   = (const float*)d_in[15];
    const float* W_out  = (const float*)d_in[16];
    float* out = (float*)d_out;

    float *p_xz, *p_xc, *p_dbc, *p_delta, *p_y, *p_yc;
    cudaGetSymbolAddress((void**)&p_xz,    g_xz);
    cudaGetSymbolAddress((void**)&p_xc,    g_xc);
    cudaGetSymbolAddress((void**)&p_dbc,   g_dbc);
    cudaGetSymbolAddress((void**)&p_delta, g_delta);
    cudaGetSymbolAddress((void**)&p_y,     g_y);
    cudaGetSymbolAddress((void**)&p_yc,    g_yc);

    // 1) xz = x @ W_in^T : [2048,1024] x [4096,1024]^T -> [2048,4096]
    sgemm_nt<128,64,16,8,4,0><<<dim3(2*CED/64, CML/128), 256>>>(
        x, CD, W_in, CD, p_xz, 2*CED, CML, 2*CED, CD, nullptr);

    // 2) conv + silu for both directions
    conv_silu_kernel<<<(2*BLED)/256, 256>>>(p_xz, conv_w, conv_b, conv_w_b, conv_b_b, p_xc);

    // 3) dbc = xc @ Wx^T : [2048,2048] x [96,2048]^T -> [2048,96] (per dir)
    sgemm_nt<64,32,16,4,4,0><<<dim3(96/32, CML/64), 128>>>(
        p_xc, CED, Wx, CED, p_dbc, 96, CML, 96, CED, nullptr);
    sgemm_nt<64,32,16,4,4,0><<<dim3(96/32, CML/64), 128>>>(
        p_xc + BLED, CED, Wx_b, CED, p_dbc + CML*96, 96, CML, 96, CED, nullptr);

    // 4) delta = softplus(dbc[:, :64] @ Wdt^T + b_dt) : K=64, N=2048 (per dir)
    sgemm_nt<128,64,16,8,4,1><<<dim3(CED/64, CML/128), 256>>>(
        p_dbc, 96, Wdt, CRK, p_delta, CED, CML, CED, CRK, b_dt);
    sgemm_nt<128,64,16,8,4,1><<<dim3(CED/64, CML/128), 256>>>(
        p_dbc + CML*96, 96, Wdt_b, CRK, p_delta + BLED, CED, CML, CED, CRK, b_dt_b);

    // 5) selective scan + gating (per dir)
    scan_kernel<<<dim3(CED/128, CB), 128>>>(
        p_delta, p_xc, p_dbc, p_xz, A_log, Dp, p_y, 0);
    scan_kernel<<<dim3(CED/128, CB), 128>>>(
        p_delta + BLED, p_xc + BLED, p_dbc + CML*96, p_xz, A_log_b, Dp_b, p_y + BLED, 1);

    // 6) combine forward + reversed backward
    combine_kernel<<<BLED/256, 256>>>(p_y, p_y + BLED, p_yc);

    // 7) out = yc @ W_out^T : [2048,2048] x [1024,2048]^T -> [2048,1024]
    sgemm_nt<128,64,16,8,4,0><<<dim3(CD/64, CML/128), 256>>>(
        p_yc, CED, W_out, CED, out, CD, CML, CD, CED, nullptr);
}

// round 2
// speedup vs baseline: 2.8547x; 2.8547x over previous
#include <cuda_runtime.h>
#include <cuda_bf16.h>
#include <cstdint>

// ---------------- Problem constants ----------------
#define CB   4
#define CL   512
#define CD   1024
#define CED  2048
#define CNS  16
#define CRK  64
#define CKC  4
#define CML  (CB*CL)        // 2048
#define BLED (CB*CL*CED)    // 4194304

// ---------------- Scratch ----------------
__device__ float g_xz[CB*CL*2*CED];
__device__ float g_xc[2*BLED];
__device__ float g_dbc[2*CML*96];
__device__ float g_delta[2*BLED];
__device__ float g_y[2*BLED];
__device__ float g_yc[BLED];
__device__ float g_xtf[CML*CD];
__device__ float g_wtf[6946816];

// weight-buffer offsets (floats)
#define OW_IN   0
#define OWX_F   4194304
#define OWX_B   4390912
#define OWDT_F  4587520
#define OWDT_B  4718592
#define OW_OUT  4849664

// ---------------- helpers ----------------
__device__ __forceinline__ float softplusf(float x) {
    return fmaxf(x, 0.f) + log1pf(__expf(-fabsf(x)));
}
__device__ __forceinline__ float siluf(float x) {
    return x / (1.f + __expf(-x));
}
__device__ __forceinline__ float tf32r(float x) {
    uint32_t r; asm("cvt.rna.tf32.f32 %0, %1;" : "=r"(r) : "f"(x));
    return __uint_as_float(r);
}
__device__ __forceinline__ float ex2f(float x) {
    float y; asm("ex2.approx.ftz.f32 %0, %1;" : "=f"(y) : "f"(x));
    return y;
}
__device__ __forceinline__ void cp16(uint32_t dst, const void* src) {
    asm volatile("cp.async.cg.shared.global [%0], [%1], 16;" :: "r"(dst), "l"(src));
}

// ---------------- elementwise kernels ----------------
__global__ void round_tf32_k(const float4* __restrict__ in, float4* __restrict__ out, int n4) {
    int i = blockIdx.x * blockDim.x + threadIdx.x;
    if (i < n4) {
        float4 v = in[i];
        v.x = tf32r(v.x); v.y = tf32r(v.y); v.z = tf32r(v.z); v.w = tf32r(v.w);
        out[i] = v;
    }
}
__global__ void zero_k(float4* __restrict__ p, int n4) {
    int i = blockIdx.x * blockDim.x + threadIdx.x;
    if (i < n4) p[i] = make_float4(0.f, 0.f, 0.f, 0.f);
}

// ---------------- TF32 tensor-core NT GEMM ----------------
// C[M,N] = A[M,K] * B[N,K]^T ; BM=128 fixed; warps 64x32; BK=32, double-buffered cp.async
// EPI: 0 none, 1 softplus(acc + bias[n]). gridDim.z>1 => split-K with atomicAdd (EPI must be 0).
template<int BN, int EPI>
__global__ void __launch_bounds__(2*(BN/32)*32)
gemm_tf32(const float* __restrict__ A, int lda,
          const float* __restrict__ B, int ldb,
          float* __restrict__ C, int ldc,
          int K, const float* __restrict__ bias)
{
    constexpr int BM = 128;
    constexpr int WARPS_N = BN/32;
    constexpr int THREADS = 2*WARPS_N*32;
    constexpr int LDK = 36;                 // 32 + 4 pad -> conflict-free frag loads
    constexpr int STAGE = (BM+BN)*LDK;
    extern __shared__ float sm[];

    const int tid  = threadIdx.x;
    const int warp = tid >> 5, lane = tid & 31;
    const int wm = warp / WARPS_N, wn = warp % WARPS_N;
    const int g = lane >> 2, t = lane & 3;
    const int row0 = blockIdx.y * BM;
    const int col0 = blockIdx.x * BN;
    const int Kc = K / gridDim.z;
    const int kbase = blockIdx.z * Kc;
    const int KT = Kc / 32;

    float acc[4][4][4];
#pragma unroll
    for (int i = 0; i < 4; i++)
#pragma unroll
        for (int j = 0; j < 4; j++) {
            acc[i][j][0]=0.f; acc[i][j][1]=0.f; acc[i][j][2]=0.f; acc[i][j][3]=0.f;
        }

    auto load_tile = [&](int kt, int s) {
        float* As = sm + s*STAGE;
        float* Bs = As + BM*LDK;
        int k0 = kbase + kt*32;
        for (int i = tid; i < BM*8; i += THREADS) {
            int m = i >> 3, kq = (i & 7) << 2;
            cp16((uint32_t)__cvta_generic_to_shared(As + m*LDK + kq),
                 A + (size_t)(row0+m)*lda + k0 + kq);
        }
        for (int i = tid; i < BN*8; i += THREADS) {
            int n = i >> 3, kq = (i & 7) << 2;
            cp16((uint32_t)__cvta_generic_to_shared(Bs + n*LDK + kq),
                 B + (size_t)(col0+n)*ldb + k0 + kq);
        }
        asm volatile("cp.async.commit_group;");
    };

    auto comp = [&](int s) {
        const float* As = sm + s*STAGE;
        const float* Bs = As + BM*LDK;
#pragma unroll
        for (int ks = 0; ks < 4; ks++) {
            int k0 = ks*8;
            uint32_t a[4][4], b[4][2];
#pragma unroll
            for (int mt = 0; mt < 4; mt++) {
                int r = (wm*64 + mt*16 + g)*LDK + k0 + t;
                a[mt][0] = __float_as_uint(As[r]);
                a[mt][1] = __float_as_uint(As[r + 8*LDK]);
                a[mt][2] = __float_as_uint(As[r + 4]);
                a[mt][3] = __float_as_uint(As[r + 8*LDK + 4]);
            }
#pragma unroll
            for (int nt = 0; nt < 4; nt++) {
                int r = (wn*32 + nt*8 + g)*LDK + k0 + t;
                b[nt][0] = __float_as_uint(Bs[r]);
                b[nt][1] = __float_as_uint(Bs[r + 4]);
            }
#pragma unroll
            for (int mt = 0; mt < 4; mt++)
#pragma unroll
                for (int nt = 0; nt < 4; nt++)
                    asm volatile(
                        "mma.sync.aligned.m16n8k8.row.col.f32.tf32.tf32.f32 "
                        "{%0,%1,%2,%3}, {%4,%5,%6,%7}, {%8,%9}, {%0,%1,%2,%3};"
                        : "+f"(acc[mt][nt][0]), "+f"(acc[mt][nt][1]),
                          "+f"(acc[mt][nt][2]), "+f"(acc[mt][nt][3])
                        : "r"(a[mt][0]), "r"(a[mt][1]), "r"(a[mt][2]), "r"(a[mt][3]),
                          "r"(b[nt][0]), "r"(b[nt][1]));
        }
    };

    load_tile(0, 0);
    for (int kt = 0; kt < KT; kt++) {
        int cur = kt & 1;
        if (kt + 1 < KT) {
            load_tile(kt + 1, cur ^ 1);
            asm volatile("cp.async.wait_group %0;" :: "n"(1));
        } else {
            asm volatile("cp.async.wait_group %0;" :: "n"(0));
        }
        __syncthreads();
        comp(cur);
        __syncthreads();
    }

    const bool use_atomic = (gridDim.z > 1);
#pragma unroll
    for (int mt = 0; mt < 4; mt++) {
        int row = row0 + wm*64 + mt*16 + g;
#pragma unroll
        for (int nt = 0; nt < 4; nt++) {
            int col = col0 + wn*32 + nt*8 + 2*t;
            float v0 = acc[mt][nt][0], v1 = acc[mt][nt][1];
            float v2 = acc[mt][nt][2], v3 = acc[mt][nt][3];
            if (EPI == 1) {
                v0 = softplusf(v0 + bias[col]);
                v1 = softplusf(v1 + bias[col+1]);
                v2 = softplusf(v2 + bias[col]);
                v3 = softplusf(v3 + bias[col+1]);
            }
            if (use_atomic) {
                atomicAdd(&C[(size_t)row*ldc + col],       v0);
                atomicAdd(&C[(size_t)row*ldc + col + 1],   v1);
                atomicAdd(&C[(size_t)(row+8)*ldc + col],   v2);
                atomicAdd(&C[(size_t)(row+8)*ldc + col+1], v3);
            } else {
                *(float2*)&C[(size_t)row*ldc + col]     = make_float2(v0, v1);
                *(float2*)&C[(size_t)(row+8)*ldc + col] = make_float2(v2, v3);
            }
        }
    }
}

// ---------------- causal depthwise conv + SiLU (both dirs), tf32-rounded out ----
__global__ void conv_silu_kernel(const float* __restrict__ xz,
                                 const float* __restrict__ cw0, const float* __restrict__ cb0,
                                 const float* __restrict__ cw1, const float* __restrict__ cb1,
                                 float* __restrict__ xc)
{
    int idx = blockIdx.x * blockDim.x + threadIdx.x;
    int e   = idx & (CED-1);
    int t   = (idx >> 11) & (CL-1);
    int b   = (idx >> 20) & (CB-1);
    int dir = idx >> 22;

    const float* w = dir ? cw1 : cw0;
    float acc = (dir ? cb1 : cb0)[e];
#pragma unroll
    for (int j = 0; j < CKC; j++) {
        int ts = t - (CKC-1) + j;
        if (ts >= 0) {
            int tg = dir ? (CL-1-ts) : ts;
            acc = fmaf(w[e*CKC + j], xz[((size_t)(b*CL + tg) << 12) + e], acc);
        }
    }
    xc[idx] = tf32r(siluf(acc));
}

// ---------------- selective scan, both dirs in one launch -----------------
#define SCAN_TC 16
__global__ void __launch_bounds__(128)
scan_kernel(const float* __restrict__ delta,
            const float* __restrict__ xc,
            const float* __restrict__ dbc,
            const float* __restrict__ xz,
            const float* __restrict__ A_log_f, const float* __restrict__ A_log_b,
            const float* __restrict__ Dp_f,    const float* __restrict__ Dp_b,
            float* __restrict__ y)
{
    __shared__ float sD[SCAN_TC][128];
    __shared__ float sX[SCAN_TC][128];
    __shared__ float sZ[SCAN_TC][128];
    __shared__ float sB[SCAN_TC][CNS];
    __shared__ float sC[SCAN_TC][CNS];

    const int e   = blockIdx.x * 128 + threadIdx.x;
    const int b   = blockIdx.y;
    const int dir = blockIdx.z;
    const int tx  = threadIdx.x;

    const float* dlt = delta + (size_t)dir * BLED;
    const float* xcd = xc    + (size_t)dir * BLED;
    const float* dbd = dbc   + (size_t)dir * CML * 96;
    float*       yd  = y     + (size_t)dir * BLED;
    const float* A_log = dir ? A_log_b : A_log_f;
    const float* Dp    = dir ? Dp_b    : Dp_f;

    float Areg[CNS];
#pragma unroll
    for (int n = 0; n < CNS; n++)
        Areg[n] = -__expf(A_log[e*CNS + n]) * 1.4426950408889634f;
    const float Dpe = Dp[e];

    float h[CNS];
#pragma unroll
    for (int n = 0; n < CNS; n++) h[n] = 0.f;

    for (int t0 = 0; t0 < CL; t0 += SCAN_TC) {
        __syncthreads();
#pragma unroll
        for (int it = 0; it < SCAN_TC; it++) {
            int t = t0 + it;
            size_t r = (size_t)(b*CL + t) * CED + e;
            sD[it][tx] = dlt[r];
            sX[it][tx] = xcd[r];
            int tz = dir ? (CL-1-t) : t;
            sZ[it][tx] = xz[((size_t)(b*CL + tz) << 12) + CED + e];
        }
        for (int j = tx; j < SCAN_TC*CNS; j += 128) {
            int it = j >> 4, n = j & (CNS-1);
            size_t r = (size_t)(b*CL + t0 + it) * 96;
            sB[it][n] = dbd[r + CRK + n];
            sC[it][n] = dbd[r + CRK + CNS + n];
        }
        __syncthreads();

#pragma unroll
        for (int it = 0; it < SCAN_TC; it++) {
            float d  = sD[it][tx];
            float xv = sX[it][tx];
            float dx = d * xv;
            float y0 = 0.f, y1 = 0.f, y2 = 0.f, y3 = 0.f;
#pragma unroll
            for (int n = 0; n < CNS; n += 4) {
                float dA0 = ex2f(d * Areg[n+0]);
                float dA1 = ex2f(d * Areg[n+1]);
                float dA2 = ex2f(d * Areg[n+2]);
                float dA3 = ex2f(d * Areg[n+3]);
                h[n+0] = fmaf(dA0, h[n+0], dx * sB[it][n+0]);
                h[n+1] = fmaf(dA1, h[n+1], dx * sB[it][n+1]);
                h[n+2] = fmaf(dA2, h[n+2], dx * sB[it][n+2]);
                h[n+3] = fmaf(dA3, h[n+3], dx * sB[it][n+3]);
                y0 = fmaf(h[n+0], sC[it][n+0], y0);
                y1 = fmaf(h[n+1], sC[it][n+1], y1);
                y2 = fmaf(h[n+2], sC[it][n+2], y2);
                y3 = fmaf(h[n+3], sC[it][n+3], y3);
            }
            float zv = sZ[it][tx];
            float yo = ((y0+y1) + (y2+y3)) + Dpe * xv;
            yd[(size_t)(b*CL + t0 + it)*CED + e] = yo * siluf(zv);
        }
    }
}

// ---------------- combine (tf32-rounded output) ------------------
__global__ void combine_kernel(const float* __restrict__ y0,
                               const float* __restrict__ y1,
                               float* __restrict__ yc)
{
    int idx = blockIdx.x * blockDim.x + threadIdx.x;
    int e = idx & (CED-1);
    int t = (idx >> 11) & (CL-1);
    int b = idx >> 20;
    float a  = y0[idx];
    float bb = y1[(size_t)(b*CL + (CL-1-t))*CED + e];
    yc[idx] = tf32r(0.5f * (a + bb));
}

// ---------------- launch ----------------
extern "C" void kernel_launch(void* const* d_in, const int* in_sizes, int n_in,
                              void* d_out, int out_size)
{
    const float* x      = (const float*)d_in[0];
    const float* W_in   = (const float*)d_in[1];
    const float* conv_w = (const float*)d_in[2];
    const float* conv_b = (const float*)d_in[3];
    const float* Wx     = (const float*)d_in[4];
    const float* Wdt    = (const float*)d_in[5];
    const float* b_dt   = (const float*)d_in[6];
    const float* A_log  = (const float*)d_in[7];
    const float* Dp     = (const float*)d_in[8];
    const float* conv_w_b = (const float*)d_in[9];
    const float* conv_b_b = (const float*)d_in[10];
    const float* Wx_b   = (const float*)d_in[11];
    const float* Wdt_b  = (const float*)d_in[12];
    const float* b_dt_b = (const float*)d_in[13];
    const float* A_log_b= (const float*)d_in[14];
    const float* Dp_b   = (const float*)d_in[15];
    const float* W_out  = (const float*)d_in[16];
    float* out = (float*)d_out;

    float *p_xz, *p_xc, *p_dbc, *p_delta, *p_y, *p_yc, *p_xtf, *p_wtf;
    cudaGetSymbolAddress((void**)&p_xz,    g_xz);
    cudaGetSymbolAddress((void**)&p_xc,    g_xc);
    cudaGetSymbolAddress((void**)&p_dbc,   g_dbc);
    cudaGetSymbolAddress((void**)&p_delta, g_delta);
    cudaGetSymbolAddress((void**)&p_y,     g_y);
    cudaGetSymbolAddress((void**)&p_yc,    g_yc);
    cudaGetSymbolAddress((void**)&p_xtf,   g_xtf);
    cudaGetSymbolAddress((void**)&p_wtf,   g_wtf);

    cudaFuncSetAttribute(gemm_tf32<128,0>, cudaFuncAttributeMaxDynamicSharedMemorySize, 73728);
    cudaFuncSetAttribute(gemm_tf32<128,1>, cudaFuncAttributeMaxDynamicSharedMemorySize, 73728);
    cudaFuncSetAttribute(gemm_tf32<96,0>,  cudaFuncAttributeMaxDynamicSharedMemorySize, 64512);
    cudaFuncSetAttribute(gemm_tf32<64,0>,  cudaFuncAttributeMaxDynamicSharedMemorySize, 55296);

    // 0) round operands to tf32
    round_tf32_k<<<(CML*CD/4 + 255)/256, 256>>>((const float4*)x, (float4*)p_xtf, CML*CD/4);
    round_tf32_k<<<(4194304/4 + 255)/256, 256>>>((const float4*)W_in,  (float4*)(p_wtf+OW_IN),  4194304/4);
    round_tf32_k<<<(196608/4  + 255)/256, 256>>>((const float4*)Wx,    (float4*)(p_wtf+OWX_F),  196608/4);
    round_tf32_k<<<(196608/4  + 255)/256, 256>>>((const float4*)Wx_b,  (float4*)(p_wtf+OWX_B),  196608/4);
    round_tf32_k<<<(131072/4  + 255)/256, 256>>>((const float4*)Wdt,   (float4*)(p_wtf+OWDT_F), 131072/4);
    round_tf32_k<<<(131072/4  + 255)/256, 256>>>((const float4*)Wdt_b, (float4*)(p_wtf+OWDT_B), 131072/4);
    round_tf32_k<<<(2097152/4 + 255)/256, 256>>>((const float4*)W_out, (float4*)(p_wtf+OW_OUT), 2097152/4);

    // 1) xz = x @ W_in^T : [2048,1024] x [4096,1024]^T
    gemm_tf32<128,0><<<dim3(32,16,1), 256, 73728>>>(
        p_xtf, CD, p_wtf+OW_IN, CD, p_xz, 2*CED, CD, nullptr);

    // 2) conv + silu (both dirs)
    conv_silu_kernel<<<(2*BLED)/256, 256>>>(p_xz, conv_w, conv_b, conv_w_b, conv_b_b, p_xc);

    // 3) dbc = xc @ Wx^T (split-K=8, atomic)
    zero_k<<<(2*CML*96/4 + 255)/256, 256>>>((float4*)p_dbc, 2*CML*96/4);
    gemm_tf32<96,0><<<dim3(1,16,8), 192, 64512>>>(
        p_xc,        CED, p_wtf+OWX_F, CED, p_dbc,           96, CED, nullptr);
    gemm_tf32<96,0><<<dim3(1,16,8), 192, 64512>>>(
        p_xc + BLED, CED, p_wtf+OWX_B, CED, p_dbc + CML*96,  96, CED, nullptr);
    round_tf32_k<<<(2*CML*96/4 + 255)/256, 256>>>((const float4*)p_dbc, (float4*)p_dbc, 2*CML*96/4);

    // 4) delta = softplus(dbc[:, :64] @ Wdt^T + b_dt)
    gemm_tf32<128,1><<<dim3(16,16,1), 256, 73728>>>(
        p_dbc,          96, p_wtf+OWDT_F, CRK, p_delta,        CED, CRK, b_dt);
    gemm_tf32<128,1><<<dim3(16,16,1), 256, 73728>>>(
        p_dbc + CML*96, 96, p_wtf+OWDT_B, CRK, p_delta + BLED, CED, CRK, b_dt_b);

    // 5) selective scan + gating, both dirs concurrently
    scan_kernel<<<dim3(CED/128, CB, 2), 128>>>(
        p_delta, p_xc, p_dbc, p_xz, A_log, A_log_b, Dp, Dp_b, p_y);

    // 6) combine
    combine_kernel<<<BLED/256, 256>>>(p_y, p_y + BLED, p_yc);

    // 7) out = yc @ W_out^T : [2048,2048] x [1024,2048]^T
    gemm_tf32<64,0><<<dim3(16,16,1), 128, 55296>>>(
        p_yc, CED, p_wtf+OW_OUT, CED, out, CD, CED, nullptr);
}